// round 12
// baseline (speedup 1.0000x reference)
#include <cuda_runtime.h>
#include <cuda_fp16.h>
#include <cstdint>

#define E_MAX 100096
#define IN_F  256
#define HID   128

// scratch (device globals = allowed scratch)
__device__ __half g_th[(size_t)E_MAX * HID];    // fp16 t (self + gather)

__device__ __forceinline__ uint32_t smem_u32(const void* p) {
    uint32_t a;
    asm("{ .reg .u64 t; cvta.to.shared.u64 t, %1; cvt.u32.u64 %0, t; }" : "=r"(a) : "l"(p));
    return a;
}
__device__ __forceinline__ void ldsm_x4(uint32_t& r0, uint32_t& r1, uint32_t& r2,
                                        uint32_t& r3, uint32_t addr) {
    asm volatile("ldmatrix.sync.aligned.m8n8.x4.shared.b16 {%0,%1,%2,%3}, [%4];"
                 : "=r"(r0), "=r"(r1), "=r"(r2), "=r"(r3) : "r"(addr));
}
__device__ __forceinline__ void mma16816(float* c, uint32_t a0, uint32_t a1,
                                         uint32_t a2, uint32_t a3,
                                         uint32_t b0, uint32_t b1) {
    asm volatile(
        "mma.sync.aligned.m16n8k16.row.col.f32.f16.f16.f32 "
        "{%0,%1,%2,%3}, {%4,%5,%6,%7}, {%8,%9}, {%0,%1,%2,%3};"
        : "+f"(c[0]), "+f"(c[1]), "+f"(c[2]), "+f"(c[3])
        : "r"(a0), "r"(a1), "r"(a2), "r"(a3), "r"(b0), "r"(b1));
}
__device__ __forceinline__ void cp_async16(uint32_t dst, const void* src) {
    asm volatile("cp.async.cg.shared.global [%0], [%1], 16;" :: "r"(dst), "l"(src));
}
#define CP_COMMIT() asm volatile("cp.async.commit_group;" ::: "memory")
#define CP_WAIT0()  asm volatile("cp.async.wait_group 0;" ::: "memory")

// =====================================================================
// t = Xh @ Wh + b : single-pass fp16 HMMA, fp32 accum.
// Full W^T fp16 resident in smem (converted ONCE per CTA from fp32 W);
// X fp32 double-buffered via cp.async; no separate W-prep kernel.
// CTA = 128x128, 8 warps (4m x 2n), BK=32.
// =====================================================================
#define BK 32
#define STR   40     // A tile row stride (halves): 80 B
#define STR_B 264    // B full-K row stride (halves): 528 B (528%128=16 -> ldsm conflict-free)

#define SM_BALL 0                       // B fp16 [128 n][264] = 67584 B
#define SM_XF   67584                   // X fp32 staging: 2 x 16384
#define SM_AH   100352                  // A fp16 tile [128][STR] = 10240
#define SMEM_BYTES 110592               // 108 KB -> 2 CTAs/SM

// one-time W [k=256][n=128] fp32 -> sB [n][k] fp16 transpose-convert
// warp w: k range (w&3)*64..+64, n half (w>>2); lane -> n pair (2 rows)
__device__ __forceinline__ void convert_B_once(char* smem,
                                               const float2* __restrict__ W2,
                                               int tid) {
    __half* sB = (__half*)(smem + SM_BALL);
    const int lane  = tid & 31;
    const int wid   = tid >> 5;
    const int kbase = (wid & 3) * 64;
    const int n0    = (wid >> 2) * 64 + lane * 2;
#pragma unroll
    for (int p = 0; p < 4; ++p) {
        const int k0 = kbase + p * 16;
        uint32_t r0[8], r1[8];
#pragma unroll
        for (int kk = 0; kk < 16; kk += 2) {
            float2 va = W2[(k0 + kk)     * (HID / 2) + (n0 >> 1)];
            float2 vb = W2[(k0 + kk + 1) * (HID / 2) + (n0 >> 1)];
            r0[kk >> 1] = ((uint32_t)__half_as_ushort(__float2half_rn(vb.x)) << 16)
                        |  __half_as_ushort(__float2half_rn(va.x));
            r1[kk >> 1] = ((uint32_t)__half_as_ushort(__float2half_rn(vb.y)) << 16)
                        |  __half_as_ushort(__float2half_rn(va.y));
        }
        uint4* d0 = (uint4*)(sB + (size_t)n0 * STR_B + k0);
        d0[0] = make_uint4(r0[0], r0[1], r0[2], r0[3]);
        d0[1] = make_uint4(r0[4], r0[5], r0[6], r0[7]);
        uint4* d1 = (uint4*)(sB + (size_t)(n0 + 1) * STR_B + k0);
        d1[0] = make_uint4(r1[0], r1[1], r1[2], r1[3]);
        d1[1] = make_uint4(r1[4], r1[5], r1[6], r1[7]);
    }
}

__device__ __forceinline__ void prefetch_X(
    uint32_t smb, int buf,
    const float4* __restrict__ X4,
    int tid, int rowBase, int kc, int E)
{
    uint32_t xdst = smb + SM_XF + buf * 16384;
#pragma unroll
    for (int it = 0; it < 4; ++it) {
        int i = it * 256 + tid;          // 1024 float4
        int r = i >> 3, f = i & 7;
        int grow = rowBase + r;
        if (grow >= E) grow = E - 1;
        cp_async16(xdst + i * 16, X4 + grow * (IN_F / 4) + kc * 8 + f);
    }
    CP_COMMIT();
}

__device__ __forceinline__ void convert_A(char* smem, int buf, int tid) {
    const float4* xf = (const float4*)(smem + SM_XF + buf * 16384);
    __half* sAh = (__half*)(smem + SM_AH);
#pragma unroll
    for (int it = 0; it < 4; ++it) {
        int i = it * 256 + tid;
        int r = i >> 3, f = i & 7;
        float4 v = xf[i];
        uint2 hp;
        hp.x = ((uint32_t)__half_as_ushort(__float2half_rn(v.y)) << 16)
             |  __half_as_ushort(__float2half_rn(v.x));
        hp.y = ((uint32_t)__half_as_ushort(__float2half_rn(v.w)) << 16)
             |  __half_as_ushort(__float2half_rn(v.z));
        *(uint2*)(sAh + r * STR + f * 4) = hp;
    }
}

__global__ __launch_bounds__(256, 2)
void gemm_mma_kernel(const float* __restrict__ X,
                     const float* __restrict__ W,
                     const float* __restrict__ bias,
                     int E) {
    extern __shared__ char smem[];

    const int tid  = threadIdx.x;
    const int wid  = tid >> 5;
    const int lane = tid & 31;
    const int wm   = wid & 3;
    const int wn   = wid >> 2;
    const int rowBase = blockIdx.x * 128;

    const float4* X4 = (const float4*)X;
    const uint32_t smb = smem_u32(smem);

    // start chunk-0 X copy, then do the one-time B convert under it
    prefetch_X(smb, 0, X4, tid, rowBase, 0, E);
    convert_B_once(smem, (const float2*)W, tid);

    float acc[2][8][4];
#pragma unroll
    for (int mi = 0; mi < 2; ++mi)
#pragma unroll
        for (int ni = 0; ni < 8; ++ni)
#pragma unroll
            for (int q = 0; q < 4; ++q) acc[mi][ni][q] = 0.f;

    const int lrow = (lane & 7) + ((lane >> 3) & 1) * 8;
    const int lkof = ((lane >> 4) & 1) * 8;

    __syncthreads();                     // B tile visible to all warps

    for (int kc = 0; kc < IN_F / BK; ++kc) {
        const int buf = kc & 1;

        CP_WAIT0();
        __syncthreads();                 // X staged data visible; A tile free

        convert_A(smem, buf, tid);

        if (kc + 1 < IN_F / BK)
            prefetch_X(smb, buf ^ 1, X4, tid, rowBase, kc + 1, E);

        __syncthreads();                 // A tile ready

        const uint32_t ah_b = smb + SM_AH;
        const uint32_t b_b  = smb + SM_BALL;

#pragma unroll
        for (int ks = 0; ks < 2; ++ks) {
            const int kg = kc * 32 + ks * 16;     // global k offset
            uint32_t af[2][4], bf[4][4];

#pragma unroll
            for (int mi = 0; mi < 2; ++mi)
                ldsm_x4(af[mi][0], af[mi][1], af[mi][2], af[mi][3],
                        ah_b + ((wm * 32 + mi * 16 + lrow) * STR + ks * 16 + lkof) * 2);
#pragma unroll
            for (int bi = 0; bi < 4; ++bi)
                ldsm_x4(bf[bi][0], bf[bi][1], bf[bi][2], bf[bi][3],
                        b_b + ((wn * 64 + bi * 16 + lrow) * STR_B + kg + lkof) * 2);
#pragma unroll
            for (int mi = 0; mi < 2; ++mi)
#pragma unroll
                for (int bi = 0; bi < 4; ++bi) {
                    mma16816(acc[mi][bi * 2 + 0], af[mi][0], af[mi][1], af[mi][2], af[mi][3],
                             bf[bi][0], bf[bi][2]);
                    mma16816(acc[mi][bi * 2 + 1], af[mi][0], af[mi][1], af[mi][2], af[mi][3],
                             bf[bi][1], bf[bi][3]);
                }
        }
        __syncthreads();                 // protect A tile before next convert
    }

    // ---- epilogue: + bias, store fp16 t ----
    const int gid = lane >> 2;
    const int cid = (lane & 3) * 2;
#pragma unroll
    for (int mi = 0; mi < 2; ++mi) {
        int row0 = rowBase + wm * 32 + mi * 16 + gid;
#pragma unroll
        for (int ni = 0; ni < 8; ++ni) {
            int col = wn * 64 + ni * 8 + cid;
            float b0 = __ldg(bias + col), b1 = __ldg(bias + col + 1);
            if (row0 < E) {
                *(__half2*)(g_th + (size_t)row0 * HID + col) =
                    __floats2half2_rn(acc[mi][ni][0] + b0, acc[mi][ni][1] + b1);
            }
            if (row0 + 8 < E) {
                *(__half2*)(g_th + (size_t)(row0 + 8) * HID + col) =
                    __floats2half2_rn(acc[mi][ni][2] + b0, acc[mi][ni][3] + b1);
            }
        }
    }
}

// =====================================================================
// out[i] = t[i] + sum_k t[nbr[i][k]] : HADD2 tree; indices via broadcast
// __ldg (no SHFL serialization) -> 16 immediately-independent gathers.
// =====================================================================
__global__ __launch_bounds__(256)
void gather_sum_kernel(const int* __restrict__ nbr,
                       float* __restrict__ out,
                       int E) {
    int gtid = blockIdx.x * blockDim.x + threadIdx.x;
    int e    = gtid >> 5;
    int lane = threadIdx.x & 31;
    if (e >= E) return;

    const uint2* H2  = (const uint2*)g_th;       // 2 half2 per uint2; 32 per row
    const uint4* nb4 = (const uint4*)nbr;        // 4 uint4 per edge row

    uint4 q0 = __ldg(nb4 + (size_t)e * 4 + 0);   // broadcast: all lanes same addr
    uint4 q1 = __ldg(nb4 + (size_t)e * 4 + 1);
    uint4 q2 = __ldg(nb4 + (size_t)e * 4 + 2);
    uint4 q3 = __ldg(nb4 + (size_t)e * 4 + 3);
    int idx[16] = {(int)q0.x, (int)q0.y, (int)q0.z, (int)q0.w,
                   (int)q1.x, (int)q1.y, (int)q1.z, (int)q1.w,
                   (int)q2.x, (int)q2.y, (int)q2.z, (int)q2.w,
                   (int)q3.x, (int)q3.y, (int)q3.z, (int)q3.w};

    uint2 s = H2[(size_t)e * 32 + lane];         // self

    uint2 v[16];
#pragma unroll
    for (int k = 0; k < 16; ++k)
        v[k] = H2[(size_t)idx[k] * 32 + lane];

    // balanced fp16 tree over the 16 neighbor rows
    __half2 tx[16], ty[16];
#pragma unroll
    for (int k = 0; k < 16; ++k) {
        tx[k] = *(const __half2*)&v[k].x;
        ty[k] = *(const __half2*)&v[k].y;
    }
#pragma unroll
    for (int stride = 8; stride >= 1; stride >>= 1)
#pragma unroll
        for (int k = 0; k < stride; ++k) {
            tx[k] = __hadd2(tx[k], tx[k + stride]);
            ty[k] = __hadd2(ty[k], ty[k + stride]);
        }

    float2 fx = __half22float2(tx[0]);
    float2 fy = __half22float2(ty[0]);
    float2 sa = __half22float2(*(const __half2*)&s.x);
    float2 sb = __half22float2(*(const __half2*)&s.y);
    float4 o;
    o.x = sa.x + fx.x;
    o.y = sa.y + fx.y;
    o.z = sb.x + fy.x;
    o.w = sb.y + fy.y;
    ((float4*)out)[(size_t)e * 32 + lane] = o;
}

extern "C" void kernel_launch(void* const* d_in, const int* in_sizes, int n_in,
                              void* d_out, int out_size) {
    const float* X   = (const float*)d_in[0];   // edge_feats [E, 256]
    const int*   nbr = (const int*)  d_in[1];   // neighbors  [E, 16]
    const float* W   = (const float*)d_in[2];   // W          [256, 128]
    const float* b   = (const float*)d_in[3];   // b          [128]
    float* out = (float*)d_out;                 // [E, 128]

    int E = in_sizes[0] / IN_F;

    cudaFuncSetAttribute(gemm_mma_kernel,
                         cudaFuncAttributeMaxDynamicSharedMemorySize, SMEM_BYTES);

    int gblocks = (E + 127) / 128;
    gemm_mma_kernel<<<gblocks, 256, SMEM_BYTES>>>(X, W, b, E);

    long long threads = (long long)E * 32;      // one warp per edge
    int blocks2 = (int)((threads + 255) / 256);
    gather_sum_kernel<<<blocks2, 256>>>(nbr, out, E);
}

// round 14
// speedup vs baseline: 1.0844x; 1.0844x over previous
#include <cuda_runtime.h>
#include <cuda_fp16.h>
#include <cstdint>

#define E_MAX 100096
#define IN_F  256
#define HID   128

// scratch (device globals = allowed scratch)
__device__ __half g_th[(size_t)E_MAX * HID];    // fp16 t (self + gather)
__device__ __half g_wh[HID * IN_F];             // W transposed [n][k], fp16

__device__ __forceinline__ uint32_t smem_u32(const void* p) {
    uint32_t a;
    asm("{ .reg .u64 t; cvta.to.shared.u64 t, %1; cvt.u32.u64 %0, t; }" : "=r"(a) : "l"(p));
    return a;
}
__device__ __forceinline__ void ldsm_x4(uint32_t& r0, uint32_t& r1, uint32_t& r2,
                                        uint32_t& r3, uint32_t addr) {
    asm volatile("ldmatrix.sync.aligned.m8n8.x4.shared.b16 {%0,%1,%2,%3}, [%4];"
                 : "=r"(r0), "=r"(r1), "=r"(r2), "=r"(r3) : "r"(addr));
}
__device__ __forceinline__ void mma16816(float* c, uint32_t a0, uint32_t a1,
                                         uint32_t a2, uint32_t a3,
                                         uint32_t b0, uint32_t b1) {
    asm volatile(
        "mma.sync.aligned.m16n8k16.row.col.f32.f16.f16.f32 "
        "{%0,%1,%2,%3}, {%4,%5,%6,%7}, {%8,%9}, {%0,%1,%2,%3};"
        : "+f"(c[0]), "+f"(c[1]), "+f"(c[2]), "+f"(c[3])
        : "r"(a0), "r"(a1), "r"(a2), "r"(a3), "r"(b0), "r"(b1));
}
__device__ __forceinline__ void cp_async16(uint32_t dst, const void* src) {
    asm volatile("cp.async.cg.shared.global [%0], [%1], 16;" :: "r"(dst), "l"(src));
}
#define CP_COMMIT() asm volatile("cp.async.commit_group;" ::: "memory")
#define CP_WAIT0()  asm volatile("cp.async.wait_group 0;" ::: "memory")

// =====================================================================
// W transpose -> fp16 (one-shot tiny kernel)
// =====================================================================
__global__ void wconv_kernel(const float* __restrict__ W) {
    int i = blockIdx.x * 256 + threadIdx.x;
    if (i >= IN_F * HID) return;
    int k = i >> 7, n = i & 127;
    g_wh[n * IN_F + k] = __float2half_rn(W[i]);
}

// =====================================================================
// t = Xh @ Wh + b : single-pass fp16 HMMA, fp32 accum  (R8/R10 structure)
// CTA = 128x128, 8 warps (4m x 2n), BK=32, cp.async double-buffered.
// =====================================================================
#define BK 32
#define STR 40                       // smem row stride (halves): 80 B
#define TILE_B (128 * STR * 2)       // 10240 B per fp16 tile

#define SM_XF 0                      // X fp32 staging: 2 x 16384
#define SM_AH 32768                  // A fp16 tile (single)
#define SM_B  43008                  // B tiles: 2 x 10240 (double-buffered)
#define SMEM_BYTES (43008 + 20480)   // 63488

__device__ __forceinline__ void prefetch_chunk(
    uint32_t smb, int buf,
    const float4* __restrict__ X4,
    const uint4* __restrict__ bh4,
    int tid, int rowBase, int kc, int E)
{
    uint32_t xdst = smb + SM_XF + buf * 16384;
#pragma unroll
    for (int it = 0; it < 4; ++it) {
        int i = it * 256 + tid;          // 1024 float4
        int r = i >> 3, f = i & 7;
        int grow = rowBase + r;
        if (grow >= E) grow = E - 1;
        cp_async16(xdst + i * 16, X4 + grow * (IN_F / 4) + kc * 8 + f);
    }
    uint32_t bdst = smb + SM_B + buf * TILE_B;
#pragma unroll
    for (int it = 0; it < 2; ++it) {
        int i = it * 256 + tid;          // 512 uint4
        int n = i >> 2, q = i & 3;
        uint32_t off = (uint32_t)(n * STR + q * 8) * 2;    // 16B-aligned
        cp_async16(bdst + off, bh4 + n * 32 + kc * 4 + q);
    }
    CP_COMMIT();
}

__device__ __forceinline__ void convert_A(char* smem, int buf, int tid) {
    const float4* xf = (const float4*)(smem + SM_XF + buf * 16384);
    __half* sAh = (__half*)(smem + SM_AH);
#pragma unroll
    for (int it = 0; it < 4; ++it) {
        int i = it * 256 + tid;
        int r = i >> 3, f = i & 7;
        float4 v = xf[i];
        uint2 hp;
        hp.x = ((uint32_t)__half_as_ushort(__float2half_rn(v.y)) << 16)
             |  __half_as_ushort(__float2half_rn(v.x));
        hp.y = ((uint32_t)__half_as_ushort(__float2half_rn(v.w)) << 16)
             |  __half_as_ushort(__float2half_rn(v.z));
        *(uint2*)(sAh + r * STR + f * 4) = hp;
    }
}

__global__ __launch_bounds__(256, 2)
void gemm_mma_kernel(const float* __restrict__ X,
                     const float* __restrict__ bias,
                     int E) {
    extern __shared__ char smem[];

    const int tid  = threadIdx.x;
    const int wid  = tid >> 5;
    const int lane = tid & 31;
    const int wm   = wid & 3;
    const int wn   = wid >> 2;
    const int rowBase = blockIdx.x * 128;

    float acc[2][8][4];
#pragma unroll
    for (int mi = 0; mi < 2; ++mi)
#pragma unroll
        for (int ni = 0; ni < 8; ++ni)
#pragma unroll
            for (int q = 0; q < 4; ++q) acc[mi][ni][q] = 0.f;

    const float4* X4  = (const float4*)X;
    const uint4*  bh4 = (const uint4*)g_wh;

    const uint32_t smb = smem_u32(smem);

    const int lrow = (lane & 7) + ((lane >> 3) & 1) * 8;
    const int lkof = ((lane >> 4) & 1) * 8;

    prefetch_chunk(smb, 0, X4, bh4, tid, rowBase, 0, E);

    for (int kc = 0; kc < IN_F / BK; ++kc) {
        const int buf = kc & 1;

        CP_WAIT0();
        __syncthreads();

        convert_A(smem, buf, tid);

        if (kc + 1 < IN_F / BK)
            prefetch_chunk(smb, buf ^ 1, X4, bh4, tid, rowBase, kc + 1, E);

        __syncthreads();

        const uint32_t ah_b = smb + SM_AH;
        const uint32_t bh_b = smb + SM_B + (uint32_t)buf * TILE_B;

#pragma unroll
        for (int ks = 0; ks < 2; ++ks) {
            const int kk = ks * 16;
            uint32_t af[2][4], bf[4][4];

#pragma unroll
            for (int mi = 0; mi < 2; ++mi)
                ldsm_x4(af[mi][0], af[mi][1], af[mi][2], af[mi][3],
                        ah_b + ((wm * 32 + mi * 16 + lrow) * STR + kk + lkof) * 2);
#pragma unroll
            for (int bi = 0; bi < 4; ++bi)
                ldsm_x4(bf[bi][0], bf[bi][1], bf[bi][2], bf[bi][3],
                        bh_b + ((wn * 64 + bi * 16 + lrow) * STR + kk + lkof) * 2);
#pragma unroll
            for (int mi = 0; mi < 2; ++mi)
#pragma unroll
                for (int bi = 0; bi < 4; ++bi) {
                    mma16816(acc[mi][bi * 2 + 0], af[mi][0], af[mi][1], af[mi][2], af[mi][3],
                             bf[bi][0], bf[bi][2]);
                    mma16816(acc[mi][bi * 2 + 1], af[mi][0], af[mi][1], af[mi][2], af[mi][3],
                             bf[bi][1], bf[bi][3]);
                }
        }
        __syncthreads();
    }

    // ---- epilogue: + bias, store fp16 t ----
    const int gid = lane >> 2;
    const int cid = (lane & 3) * 2;
#pragma unroll
    for (int mi = 0; mi < 2; ++mi) {
        int row0 = rowBase + wm * 32 + mi * 16 + gid;
#pragma unroll
        for (int ni = 0; ni < 8; ++ni) {
            int col = wn * 64 + ni * 8 + cid;
            float b0 = __ldg(bias + col), b1 = __ldg(bias + col + 1);
            if (row0 < E) {
                *(__half2*)(g_th + (size_t)row0 * HID + col) =
                    __floats2half2_rn(acc[mi][ni][0] + b0, acc[mi][ni][1] + b1);
            }
            if (row0 + 8 < E) {
                *(__half2*)(g_th + (size_t)(row0 + 8) * HID + col) =
                    __floats2half2_rn(acc[mi][ni][2] + b0, acc[mi][ni][3] + b1);
            }
        }
    }
}

// =====================================================================
// out[i] = t[i] + sum_k t[nbr[i][k]] : 2 edges per warp, 16 lanes/edge,
// uint4 (16B) gathers, HADD2 tree in 2 batches of 8.
// Row = 128 halves = 256 B = 16 uint4  (R12 bug: used stride 8)
// =====================================================================
__device__ __forceinline__ uint4 hadd2_u4(uint4 a, uint4 b) {
    uint4 r;
    *(__half2*)&r.x = __hadd2(*(__half2*)&a.x, *(__half2*)&b.x);
    *(__half2*)&r.y = __hadd2(*(__half2*)&a.y, *(__half2*)&b.y);
    *(__half2*)&r.z = __hadd2(*(__half2*)&a.z, *(__half2*)&b.z);
    *(__half2*)&r.w = __hadd2(*(__half2*)&a.w, *(__half2*)&b.w);
    return r;
}

__global__ __launch_bounds__(256)
void gather_sum_kernel(const int* __restrict__ nbr,
                       float* __restrict__ out,
                       int E) {
    int warp = (blockIdx.x * blockDim.x + threadIdx.x) >> 5;
    int lane = threadIdx.x & 31;
    int half = lane >> 4;                 // which edge within the warp
    int hl   = lane & 15;                 // lane within the half-warp
    int e    = warp * 2 + half;
    bool valid = (e < E);
    int ec = valid ? e : (E - 1);
    if (warp * 2 >= E) return;

    const uint4* H4 = (const uint4*)g_th;     // 16 uint4 per 128-half row

    // lanes 0-15 hold edge A's 16 indices, lanes 16-31 edge B's
    int j = nbr[(size_t)ec * 16 + hl];

    uint4 s = H4[(size_t)ec * 16 + hl];       // self row segment

    const unsigned srcBase = lane & 16;       // shfl source base for own edge

    // batch 1: neighbors 0..7
    uint4 u[8];
#pragma unroll
    for (int k = 0; k < 8; ++k) {
        int n = __shfl_sync(0xffffffffu, j, srcBase + k);
        u[k] = H4[(size_t)n * 16 + hl];
    }
#pragma unroll
    for (int st = 4; st >= 1; st >>= 1)
#pragma unroll
        for (int k = 0; k < st; ++k) u[k] = hadd2_u4(u[k], u[k + st]);
    uint4 accA = u[0];

    // batch 2: neighbors 8..15
#pragma unroll
    for (int k = 0; k < 8; ++k) {
        int n = __shfl_sync(0xffffffffu, j, srcBase + 8 + k);
        u[k] = H4[(size_t)n * 16 + hl];
    }
#pragma unroll
    for (int st = 4; st >= 1; st >>= 1)
#pragma unroll
        for (int k = 0; k < st; ++k) u[k] = hadd2_u4(u[k], u[k + st]);

    uint4 acc = hadd2_u4(accA, u[0]);         // tree depth 4, balanced

    if (valid) {
        // fp32 combine with self, 8 outputs per lane
        float2 g0 = __half22float2(*(__half2*)&acc.x);
        float2 g1 = __half22float2(*(__half2*)&acc.y);
        float2 g2 = __half22float2(*(__half2*)&acc.z);
        float2 g3 = __half22float2(*(__half2*)&acc.w);
        float2 s0 = __half22float2(*(__half2*)&s.x);
        float2 s1 = __half22float2(*(__half2*)&s.y);
        float2 s2 = __half22float2(*(__half2*)&s.z);
        float2 s3 = __half22float2(*(__half2*)&s.w);
        float4 o0 = {s0.x + g0.x, s0.y + g0.y, s1.x + g1.x, s1.y + g1.y};
        float4 o1 = {s2.x + g2.x, s2.y + g2.y, s3.x + g3.x, s3.y + g3.y};
        float4* dst = (float4*)(out + (size_t)e * HID + hl * 8);
        dst[0] = o0;
        dst[1] = o1;
    }
}

extern "C" void kernel_launch(void* const* d_in, const int* in_sizes, int n_in,
                              void* d_out, int out_size) {
    const float* X   = (const float*)d_in[0];   // edge_feats [E, 256]
    const int*   nbr = (const int*)  d_in[1];   // neighbors  [E, 16]
    const float* W   = (const float*)d_in[2];   // W          [256, 128]
    const float* b   = (const float*)d_in[3];   // b          [128]
    float* out = (float*)d_out;                 // [E, 128]

    int E = in_sizes[0] / IN_F;

    cudaFuncSetAttribute(gemm_mma_kernel,
                         cudaFuncAttributeMaxDynamicSharedMemorySize, SMEM_BYTES);

    wconv_kernel<<<(IN_F * HID + 255) / 256, 256>>>(W);

    int gblocks = (E + 127) / 128;
    gemm_mma_kernel<<<gblocks, 256, SMEM_BYTES>>>(X, b, E);

    int warps   = (E + 1) / 2;                  // 2 edges per warp
    int blocks2 = (warps * 32 + 255) / 256;
    gather_sum_kernel<<<blocks2, 256>>>(nbr, out, E);
}